// round 12
// baseline (speedup 1.0000x reference)
#include <cuda_runtime.h>

// Fixed problem shapes
#define B_  2048
#define T_  32
#define K_  1024
#define D_  256

#define BM 64             // batch rows per block (8 warps x 8 rows)
#define BN 512            // codes per n-chunk (32 lanes x 16 cols)
#define BD 32             // reduction chunk
#define NCHUNK (K_ / BN)  // 2
#define DCHUNK (D_ / BD)  // 8
#define NCI (NCHUNK * DCHUNK)  // 16 chunks

// Precomputed per-code squared norms: c_sq[t*K + k]
__device__ float g_csq[T_ * K_];

typedef unsigned long long ull;

__device__ __forceinline__ ull pack2(float v) {          // (v, v)
    ull r;
    asm("mov.b64 %0, {%1, %1};" : "=l"(r) : "f"(v));
    return r;
}
__device__ __forceinline__ void unpack2(ull v, float& lo, float& hi) {
    asm("mov.b64 {%0, %1}, %2;" : "=f"(lo), "=f"(hi) : "l"(v));
}
__device__ __forceinline__ void ffma2(ull& d, ull a, ull b) {
    asm("fma.rn.f32x2 %0, %1, %2, %0;" : "+l"(d) : "l"(a), "l"(b));
}

// ---------------------------------------------------------------------------
__global__ void csq_kernel(const float* __restrict__ cb) {
    int warp = (blockIdx.x * blockDim.x + threadIdx.x) >> 5;
    int lane = threadIdx.x & 31;
    if (warp >= T_ * K_) return;
    const float4* row = (const float4*)(cb + (size_t)warp * D_);
    float s = 0.f;
#pragma unroll
    for (int i = 0; i < 2; i++) {
        float4 v = row[lane + i * 32];
        s += v.x * v.x + v.y * v.y + v.z * v.z + v.w * v.w;
    }
#pragma unroll
    for (int off = 16; off; off >>= 1)
        s += __shfl_down_sync(0xffffffffu, s, off);
    if (lane == 0) g_csq[warp] = s;
}

// ---------------------------------------------------------------------------
// Block = (64 batch rows, one t). 256 threads, 1 CTA/SM.
// Per-thread 8x16 microtile (4 col-bands of 4): FMA-bound by model.
//   Xs [d][m]  64 KB resident (a: 2 broadcast LDS.128 per d, dup'd via mov)
//   Cs [d][k]  2 x 64 KB double buffer; b: 4 conflict-free LDS.128 per d,
//              consumed as natural column pairs (zero movs).
// C staging software-pipelined in 4 register waves per chunk.
// Running argmin of c_sq - 2*dot (x_sq dropped: argmin-invariant).
// ---------------------------------------------------------------------------
extern __shared__ float smem[];

// store one staged wave: 16 d-values of code k into dst[(dl+j)*BN + k]
#define ST16(dst, k, dl, pf)                                                  \
    do {                                                                      \
        _Pragma("unroll")                                                     \
        for (int q_ = 0; q_ < 4; q_++) {                                      \
            (dst)[((dl) + q_ * 4 + 0) * BN + (k)] = (pf)[q_].x;               \
            (dst)[((dl) + q_ * 4 + 1) * BN + (k)] = (pf)[q_].y;               \
            (dst)[((dl) + q_ * 4 + 2) * BN + (k)] = (pf)[q_].z;               \
            (dst)[((dl) + q_ * 4 + 3) * BN + (k)] = (pf)[q_].w;               \
        }                                                                     \
    } while (0)

#define LD4(pf, src)                                                          \
    do {                                                                      \
        _Pragma("unroll")                                                     \
        for (int q_ = 0; q_ < 4; q_++) (pf)[q_] = ((const float4*)(src))[q_]; \
    } while (0)

__global__ __launch_bounds__(256) void vsq_kernel(
    const float* __restrict__ x,     // [B, T, D]
    const float* __restrict__ cb,    // [T, K, D]
    float* __restrict__ out)         // [B*T*D embed][B*T idx-as-float]
{
    float* Xs    = smem;                     // [256][64]  = 64 KB
    float* Cs0   = Xs + D_ * BM;             // [32][512]  = 64 KB
    float* Cs1   = Cs0 + BD * BN;            // 64 KB
    float* s_csq = Cs1 + BD * BN;            // [1024] 4 KB
    int*   s_idx = (int*)(s_csq + K_);       // [64]

    const int t   = blockIdx.y;
    const int b0  = blockIdx.x * BM;
    const int tid = threadIdx.x;
    const int lane = tid & 31;
    const int wid  = tid >> 5;               // warp owns rows wid*8..+7
    const int m0   = wid * 8;
    const int lane4 = lane * 4;

    const float* cbT = cb + (size_t)t * K_ * D_;

    // ---- stage c_sq row for this t ----
#pragma unroll
    for (int i = 0; i < K_ / 256; i++)
        s_csq[tid + i * 256] = g_csq[t * K_ + tid + i * 256];

    // ---- Load X tile transposed: Xs[d][m] (4 threads per row) ----
    {
        const int m  = tid & 63;
        const int qd = tid >> 6;             // d-quarter 0..3
        const float4* xg =
            (const float4*)(x + ((size_t)(b0 + m) * T_ + t) * D_ + qd * 64);
#pragma unroll
        for (int j4 = 0; j4 < 16; j4++) {
            float4 v = xg[j4];
            int d = qd * 64 + j4 * 4;
            Xs[(d + 0) * BM + m] = v.x;
            Xs[(d + 1) * BM + m] = v.y;
            Xs[(d + 2) * BM + m] = v.z;
            Xs[(d + 3) * BM + m] = v.w;
        }
    }

    // ---- prologue: stage chunk 0 into Cs0 (codes tid and tid+256, d 0..31) --
    {
        float4 pf[4];
        const float* s1 = cbT + (size_t)tid * D_;
        const float* s2 = cbT + (size_t)(tid + 256) * D_;
        LD4(pf, s1);      ST16(Cs0, tid, 0, pf);
        LD4(pf, s1 + 16); ST16(Cs0, tid, 16, pf);
        LD4(pf, s2);      ST16(Cs0, tid + 256, 0, pf);
        LD4(pf, s2 + 16); ST16(Cs0, tid + 256, 16, pf);
    }

    float best_val[8];
    int   best_idx[8];
#pragma unroll
    for (int i = 0; i < 8; i++) { best_val[i] = 3.4e38f; best_idx[i] = 0; }

#pragma unroll 1
    for (int nci = 0; nci < NCHUNK; nci++) {
        ull acc[4][8][2];                    // [band g][row r][col-pair jp]
#pragma unroll
        for (int g = 0; g < 4; g++)
#pragma unroll
            for (int r = 0; r < 8; r++) { acc[g][r][0] = 0ull; acc[g][r][1] = 0ull; }

#pragma unroll 1
        for (int dci = 0; dci < DCHUNK; dci++) {
            const int ci = nci * DCHUNK + dci;
            __syncthreads();                  // Cs[ci&1] ready; other buffer free

            const float* Csc  = (ci & 1) ? Cs1 : Cs0;
            float*       Cdst = (ci & 1) ? Cs0 : Cs1;
            const bool   more = (ci + 1 < NCI);
            const int    nc2  = ((ci + 1) >> 3) * BN;
            const int    dc2  = ((ci + 1) & 7) * BD;
            const float* src1 = cbT + (size_t)(nc2 + tid) * D_ + dc2;
            const float* src2 = cbT + (size_t)(nc2 + 256 + tid) * D_ + dc2;
            const int    dc   = dci * BD;

            float4 pfA[4], pfB[4];

#pragma unroll
            for (int q = 0; q < 8; q++) {
                // staging hooks (compile-time q, runtime 'more' predicate)
                if (q == 0) { if (more) LD4(pfA, src1); }
                if (q == 2) { if (more) { ST16(Cdst, tid, 0, pfA);        LD4(pfB, src1 + 16); } }
                if (q == 4) { if (more) { ST16(Cdst, tid, 16, pfB);       LD4(pfA, src2); } }
                if (q == 6) { if (more) { ST16(Cdst, tid + 256, 0, pfA);  LD4(pfB, src2 + 16); } }

#pragma unroll 1
                for (int dd = 0; dd < 4; dd++) {
                    const int d = q * 4 + dd;
                    const float* Cd = Csc + d * BN;

                    // b: 4 conflict-free LDS.128, natural col pairs
                    double2 b0 = *(const double2*)(Cd +   0 + lane4);
                    double2 b1 = *(const double2*)(Cd + 128 + lane4);
                    double2 b2 = *(const double2*)(Cd + 256 + lane4);
                    double2 b3 = *(const double2*)(Cd + 384 + lane4);
                    ull bb[4][2] = {
                        {__double_as_longlong(b0.x), __double_as_longlong(b0.y)},
                        {__double_as_longlong(b1.x), __double_as_longlong(b1.y)},
                        {__double_as_longlong(b2.x), __double_as_longlong(b2.y)},
                        {__double_as_longlong(b3.x), __double_as_longlong(b3.y)}};

                    // a: 2 broadcast LDS.128, duplicated per row via mov.b64
                    const float4* Xd = (const float4*)(Xs + (dc + d) * BM + m0);
                    float4 a03 = Xd[0], a47 = Xd[1];
                    ull aaP[8] = {pack2(a03.x), pack2(a03.y), pack2(a03.z), pack2(a03.w),
                                  pack2(a47.x), pack2(a47.y), pack2(a47.z), pack2(a47.w)};

#pragma unroll
                    for (int g = 0; g < 4; g++)
#pragma unroll
                        for (int r = 0; r < 8; r++) {
                            ffma2(acc[g][r][0], aaP[r], bb[g][0]);
                            ffma2(acc[g][r][1], aaP[r], bb[g][1]);
                        }
                }
            }
            if (more) ST16(Cdst, tid + 256, 16, pfB);
        }

        // ---- scores + running argmin (n ascending per thread per row) ----
#pragma unroll
        for (int g = 0; g < 4; g++)
#pragma unroll
            for (int jp = 0; jp < 2; jp++) {
                const int n0 = nci * BN + g * 128 + lane4 + jp * 2;
                const float cs0 = s_csq[n0];
                const float cs1 = s_csq[n0 + 1];
#pragma unroll
                for (int r = 0; r < 8; r++) {
                    float d0, d1;
                    unpack2(acc[g][r][jp], d0, d1);
                    float s0 = fmaf(-2.f, d0, cs0);
                    float s1 = fmaf(-2.f, d1, cs1);
                    if (s0 < best_val[r]) { best_val[r] = s0; best_idx[r] = n0; }
                    if (s1 < best_val[r]) { best_val[r] = s1; best_idx[r] = n0 + 1; }
                }
            }
    }

    // ---- argmin across lanes: warp shuffle (warp owns its 8 rows) ----
#pragma unroll
    for (int i = 0; i < 8; i++) {
        float bv = best_val[i];
        int   bi = best_idx[i];
#pragma unroll
        for (int off = 16; off; off >>= 1) {
            float ov = __shfl_down_sync(0xffffffffu, bv, off);
            int   oi = __shfl_down_sync(0xffffffffu, bi, off);
            if (ov < bv || (ov == bv && oi < bi)) { bv = ov; bi = oi; }
        }
        if (lane == 0) {
            s_idx[m0 + i] = bi;
            out[(size_t)B_ * T_ * D_ + (size_t)(b0 + m0 + i) * T_ + t] = (float)bi;
        }
    }
    __syncthreads();

    // ---- embed gather: 4 threads per row, 16 float4 each ----
    {
        const int r = tid >> 2;               // 0..63
        const int p = tid & 3;                // 0..3
        const int kidx = s_idx[r];
        const float4* src = (const float4*)(cbT + (size_t)kidx * D_) + p * 16;
        float4* dst = (float4*)(out + ((size_t)(b0 + r) * T_ + t) * D_) + p * 16;
#pragma unroll
        for (int q = 0; q < 16; q++)
            dst[q] = src[q];
    }
}

// ---------------------------------------------------------------------------
extern "C" void kernel_launch(void* const* d_in, const int* in_sizes, int n_in,
                              void* d_out, int out_size) {
    const float* x  = (const float*)d_in[0];   // input   [B, T, D]
    const float* cb = (const float*)d_in[1];   // codebook[T, K, D]
    float* out = (float*)d_out;

    {
        int warps   = T_ * K_;
        int threads = 256;
        int blocks  = (warps * 32 + threads - 1) / threads;
        csq_kernel<<<blocks, threads>>>(cb);
    }

    {
        // Xs 64KB + 2 x Cs 64KB + csq 4KB + s_idx = ~196.25 KB
        size_t shmem = (size_t)(D_ * BM + 2 * BD * BN + K_) * sizeof(float)
                     + BM * sizeof(int);
        cudaFuncSetAttribute(vsq_kernel,
                             cudaFuncAttributeMaxDynamicSharedMemorySize,
                             (int)shmem);
        dim3 grid(B_ / BM, T_);
        vsq_kernel<<<grid, 256, shmem>>>(x, cb, out);
    }
}